// round 11
// baseline (speedup 1.0000x reference)
#include <cuda_runtime.h>
#include <cuda_fp16.h>
#include <cstdint>

#define NB 4
#define NC 64
#define NH 64
#define NW 64
#define NHW 4096

// ---- packed fp32x2 helpers (PTX-only; ptxas never auto-fuses) ----
#define PACK2(d, v)   asm("mov.b64 %0, {%1, %1};" : "=l"(d) : "r"(__float_as_uint(v)))
#define UNPACK2(l_, h_, in_) do { unsigned _ulo, _uhi; \
    asm("mov.b64 {%0, %1}, %2;" : "=r"(_ulo), "=r"(_uhi) : "l"(in_)); \
    l_ = __uint_as_float(_ulo); h_ = __uint_as_float(_uhi); } while (0)
#define FMA2(d, a, b, c) asm("fma.rn.f32x2 %0, %1, %2, %3;" : "=l"(d) : "l"(a), "l"(b), "l"(c))
#define MUL2(d, a, b)    asm("mul.rn.f32x2 %0, %1, %2;"     : "=l"(d) : "l"(a), "l"(b))

static __device__ __forceinline__ half2 u2h2(unsigned u) {
    return *reinterpret_cast<half2*>(&u);
}

// ---------------- device scratch (no allocations allowed anywhere) ----------------
__device__ __align__(16) __half g_xT[NB*NHW*NC];     // x in NHWC, fp16 (gather source)
__device__ __align__(16) float g_attn0[NB*NC*NHW];   // attn after deform0, NCHW fp32
__device__ __align__(16) __half g_attn0T[NB*NHW*NC]; // attn after deform0, NHWC fp16
__device__ __align__(16) float g_off0 [NB*50*NHW];   // partial (c 0..31) + bias
__device__ __align__(16) float g_off0b[NB*50*NHW];   // partial (c 32..63)
__device__ __align__(16) float g_off1 [NB*98*NHW];
__device__ __align__(16) float g_off1b[NB*98*NHW];
__device__ __align__(16) float g_wT0[576*52];        // [c*9+tap][o] padded 50->52
__device__ __align__(16) float g_wT1[576*100 + 64];  // padded 98->100 (+guard)
__device__ __align__(16) float g_wdw0T[25*64];       // [k][c]
__device__ __align__(16) float g_wdw1T[49*64];       // [k][c]
__device__ __align__(16) float g_wpwT[64*64];        // [c][o]

// ---------------- merged weight repack + NCHW->NHWC fp16 transpose ----------------
__global__ void prep_transpose_kernel(const float* __restrict__ x,
                                      const float* __restrict__ w_off0,
                                      const float* __restrict__ w_off1,
                                      const float* __restrict__ w_dw0,
                                      const float* __restrict__ w_dw1,
                                      const float* __restrict__ w_pw) {
    __shared__ float sm[64*65];
    if (blockIdx.x < 256) {
        int bh = blockIdx.x;
        int b = bh >> 6, h = bh & 63;
        int tid = threadIdx.x;
        for (int i = tid; i < 4096; i += 256) {
            int c = i >> 6, w = i & 63;
            sm[c*65 + w] = x[((b*64 + c)*64 + h)*64 + w];
        }
        __syncthreads();
        for (int i = tid; i < 4096; i += 256) {
            int w = i >> 6, c = i & 63;
            g_xT[(b*4096 + h*64 + w)*64 + c] = __float2half_rn(sm[c*65 + w]);
        }
    } else {
        int i = (blockIdx.x - 256) * 256 + threadIdx.x;
        if (i < 576*52) {
            int r = i / 52, o = i % 52, c = r / 9, t = r % 9;
            g_wT0[i] = (o < 50) ? w_off0[(o*64 + c)*9 + t] : 0.f;
        }
        if (i < 576*100) {
            int r = i / 100, o = i % 100, c = r / 9, t = r % 9;
            g_wT1[i] = (o < 98) ? w_off1[(o*64 + c)*9 + t] : 0.f;
        }
        if (i < 25*64) { int k = i >> 6, c = i & 63; g_wdw0T[i] = w_dw0[c*25 + k]; }
        if (i < 49*64) { int k = i >> 6, c = i & 63; g_wdw1T[i] = w_dw1[c*49 + k]; }
        if (i < 4096)  { int c = i >> 6, o = i & 63; g_wpwT[i]  = w_pw[o*64 + c]; }
    }
}

// ---------------- 3x3 offset conv (pad=1), split-C partials, f32x2 ----------------
__global__ void offconv_kernel(const float* __restrict__ xin,
                               const float* __restrict__ bias, int which) {
    __shared__ float xs[3*32*68];   // 26112 bytes
    const int tx = threadIdx.x, ty = threadIdx.y;
    const int tid = ty*16 + tx;     // blockDim (16,13) = 208 threads
    const int b = blockIdx.y, h = blockIdx.x;
    const int half_ = blockIdx.z & 1;
    const int ogrp  = blockIdx.z >> 1;
    const float* src = which ? (const float*)g_attn0 : xin;

    const float* wT = which ? (const float*)g_wT1 : (const float*)g_wT0;
    const int OPAD = which ? 100 : 52;
    const int O    = which ? 98  : 50;
    float* outp;
    if (which) outp = half_ ? (float*)g_off1b : (float*)g_off1;
    else       outp = half_ ? (float*)g_off0b : (float*)g_off0;

    int o4 = ogrp*52 + ty*4;
    const bool active = (o4 + 4 <= OPAD);
    if (!active) o4 = 0;            // compute harmlessly, never store
    const float* wbase = wT + o4;

    for (int i = tid; i < 3*32*64; i += 208) {
        int r = i >> 11, rem = i & 2047, c = rem >> 6, w = rem & 63;
        int hh = h + r - 1;
        float v = 0.f;
        if (hh >= 0 && hh < 64) v = src[((b*64 + (half_*32 + c))*64 + hh)*64 + w];
        xs[(r*32 + c)*68 + w + 1] = v;
    }
    for (int i = tid; i < 96; i += 208) {
        int base = i * 68;
        xs[base] = 0.f; xs[base+65] = 0.f; xs[base+66] = 0.f; xs[base+67] = 0.f;
    }
    __syncthreads();

    unsigned long long acc[4][2];
    unsigned long long z; PACK2(z, 0.f);
#pragma unroll
    for (int j = 0; j < 4; ++j) { acc[j][0] = z; acc[j][1] = z; }

    for (int c = 0; c < 32; ++c) {
        const float* xrow = xs + c*68 + 4*tx;
        const float* wrow = wbase + (half_*32 + c)*9*OPAD;
#pragma unroll
        for (int dy = 0; dy < 3; ++dy) {
            float4 A  = *(const float4*)(xrow + dy*(32*68));
            float2 Bv = *(const float2*)(xrow + dy*(32*68) + 4);
            float v[6] = {A.x, A.y, A.z, A.w, Bv.x, Bv.y};
            unsigned long long vv[6];
#pragma unroll
            for (int j = 0; j < 6; ++j) PACK2(vv[j], v[j]);
#pragma unroll
            for (int dx = 0; dx < 3; ++dx) {
                ulonglong2 wv = *(const ulonglong2*)(wrow + (dy*3 + dx)*OPAD);
#pragma unroll
                for (int j = 0; j < 4; ++j) {
                    FMA2(acc[j][0], vv[j+dx], wv.x, acc[j][0]);
                    FMA2(acc[j][1], vv[j+dx], wv.y, acc[j][1]);
                }
            }
        }
    }

    if (active) {
        float a0, a1, a2, a3;
#pragma unroll
        for (int j = 0; j < 4; ++j) {
            UNPACK2(a0, a1, acc[j][0]);
            UNPACK2(a2, a3, acc[j][1]);
            float r4[4] = {a0, a1, a2, a3};
#pragma unroll
            for (int oo = 0; oo < 4; ++oo) {
                int o = o4 + oo;
                if (o >= O) break;
                float bb = half_ ? 0.f : bias[o];
                outp[((b*O + o)*64 + h)*64 + 4*tx + j] = r4[oo] + bb;
            }
        }
    }
}

// ---------------- deform5: K=5 dil=1, 4 channels/thread, 32 pixels/block ----------------
// Block (16,32) = 512 threads; grid (2, 64, NB) -> 512 blocks (single wave).
__global__ void __launch_bounds__(512) deform5_kernel(const float* __restrict__ bdw) {
    constexpr int K = 5, DIL = 1, K2 = 25, PAD = 2, E = K2 * 32;
    __shared__ __align__(16) int4  s_i4[E];                  // 12.8 KB
    __shared__ __align__(16) half2 s_wh[E][4];               // 12.8 KB
    __shared__ float s_wdw[K2*64];                           // 6.4 KB

    const int tx = threadIdx.x;          // channel quad: 4tx..4tx+3
    const int p  = threadIdx.y;          // pixel 0..31
    const int tid = p*16 + tx;
    const int b = blockIdx.z, h = blockIdx.y, w0 = blockIdx.x * 32;

    for (int i = tid; i < K2*64; i += 512) s_wdw[i] = g_wdw0T[i];

    // stage 1
    const float* offA = (const float*)g_off0  + (size_t)(b*2*K2)*4096 + h*64 + w0;
    const float* offB = (const float*)g_off0b + (size_t)(b*2*K2)*4096 + h*64 + w0;
    for (int e = tid; e < E; e += 512) {
        int k = e >> 5, pp = e & 31;
        float oy = offA[(2*k)*4096   + pp] + offB[(2*k)*4096   + pp];
        float ox = offA[(2*k+1)*4096 + pp] + offB[(2*k+1)*4096 + pp];
        float py = (float)(h - PAD + DIL*(k/K)) + oy;
        float px = (float)(w0 + pp - PAD + DIL*(k%K)) + ox;
        float fy = floorf(py), fx = floorf(px);
        float wy1 = py - fy, wx1 = px - fx;
        int y0 = (int)fy, x0i = (int)fx;
        bool yv0 = (unsigned)y0        < 64u;
        bool yv1 = (unsigned)(y0 + 1)  < 64u;
        bool xv0 = (unsigned)x0i       < 64u;
        bool xv1 = (unsigned)(x0i + 1) < 64u;
        int yc0 = min(max(y0, 0), 63),  yc1 = min(max(y0 + 1, 0), 63);
        int xc0 = min(max(x0i, 0), 63), xc1 = min(max(x0i + 1, 0), 63);
        float wy0f = 1.f - wy1, wx0f = 1.f - wx1;
        s_i4[e] = make_int4(yc0*4096 + xc0*64, yc0*4096 + xc1*64,
                            yc1*4096 + xc0*64, yc1*4096 + xc1*64);
        float m00 = (yv0 && xv0) ? wy0f*wx0f : 0.f;
        float m01 = (yv0 && xv1) ? wy0f*wx1  : 0.f;
        float m10 = (yv1 && xv0) ? wy1 *wx0f : 0.f;
        float m11 = (yv1 && xv1) ? wy1 *wx1  : 0.f;
        s_wh[e][0] = __floats2half2_rn(m00, m00);
        s_wh[e][1] = __floats2half2_rn(m01, m01);
        s_wh[e][2] = __floats2half2_rn(m10, m10);
        s_wh[e][3] = __floats2half2_rn(m11, m11);
    }
    __syncthreads();

    // stage 2: 4 channels per thread (uint2 = 2x half2 per gather)
    const __half* base = (const __half*)g_xT + (size_t)b*262144 + 4*tx;
    float a0 = 0.f, a1 = 0.f, a2 = 0.f, a3 = 0.f;
#pragma unroll 5
    for (int k = 0; k < K2; ++k) {
        int e = (k << 5) | p;
        int4  I = s_i4[e];
        half2 W0 = s_wh[e][0], W1 = s_wh[e][1], W2 = s_wh[e][2], W3 = s_wh[e][3];
        uint2 u00 = *(const uint2*)(base + I.x);
        uint2 u01 = *(const uint2*)(base + I.y);
        uint2 u10 = *(const uint2*)(base + I.z);
        uint2 u11 = *(const uint2*)(base + I.w);
        half2 vlo = __hmul2(u2h2(u00.x), W0);
        vlo = __hfma2(u2h2(u01.x), W1, vlo);
        vlo = __hfma2(u2h2(u10.x), W2, vlo);
        vlo = __hfma2(u2h2(u11.x), W3, vlo);
        half2 vhi = __hmul2(u2h2(u00.y), W0);
        vhi = __hfma2(u2h2(u01.y), W1, vhi);
        vhi = __hfma2(u2h2(u10.y), W2, vhi);
        vhi = __hfma2(u2h2(u11.y), W3, vhi);
        float2 flo = __half22float2(vlo);
        float2 fhi = __half22float2(vhi);
        float4 wd = *(const float4*)(s_wdw + k*64 + 4*tx);
        a0 += flo.x * wd.x;
        a1 += flo.y * wd.y;
        a2 += fhi.x * wd.z;
        a3 += fhi.y * wd.w;
    }
    float4 bd = *(const float4*)(bdw + 4*tx);
    a0 += bd.x; a1 += bd.y; a2 += bd.z; a3 += bd.w;

    // NHWC fp16 store (coalesced)
    uint2 hv;
    hv.x = *reinterpret_cast<unsigned*>(&(*(half2*)&hv.x = __floats2half2_rn(a0, a1), hv.x));
    // (write via explicit temp to keep it simple)
    half2 t0 = __floats2half2_rn(a0, a1);
    half2 t1 = __floats2half2_rn(a2, a3);
    hv.x = *reinterpret_cast<unsigned*>(&t0);
    hv.y = *reinterpret_cast<unsigned*>(&t1);
    *(uint2*)(g_attn0T + (size_t)(b*4096 + h*64 + w0 + p)*64 + 4*tx) = hv;

    // NCHW fp32 store via smem transpose (alias s_i4; done reading it)
    __syncthreads();
    float* s_t = (float*)&s_i4[0];       // [p][c] stride 68 (8.7 KB < 12.8 KB)
    *(float4*)(s_t + p*68 + 4*tx) = make_float4(a0, a1, a2, a3);
    __syncthreads();
    for (int v = tid; v < 2048; v += 512) {
        int c = v >> 5, pp = v & 31;
        g_attn0[((b*64 + c)*64 + h)*64 + w0 + pp] = s_t[pp*68 + c];
    }
}

// ---------------- deform7: K=7 dil=3, 2 ch/thread, 16 px/block, fused 1x1 ----------------
__global__ void __launch_bounds__(512) deform7_kernel(const float* __restrict__ bdw,
                                                      float* __restrict__ outF,
                                                      const float* __restrict__ x,
                                                      const float* __restrict__ bpw) {
    constexpr int K = 7, DIL = 3, K2 = 49, PAD = 9, E = K2 * 16;
    __shared__ __align__(16) int4  s_i4[E];                  // 12.5 KB
    __shared__ __align__(16) half2 s_wh[E][4];               // 12.5 KB
    __shared__ float s_wdw[K2*64];                           // 12.5 KB

    const int tx = threadIdx.x;          // channel pair: 2tx, 2tx+1
    const int p  = threadIdx.y;          // pixel 0..15
    const int tid = p*32 + tx;
    const int b = blockIdx.z, h = blockIdx.y, w0 = blockIdx.x * 16;

    for (int i = tid; i < K2*64; i += 512) s_wdw[i] = g_wdw1T[i];

    // stage 1
    const float* offA = (const float*)g_off1  + (size_t)(b*2*K2)*4096 + h*64 + w0;
    const float* offB = (const float*)g_off1b + (size_t)(b*2*K2)*4096 + h*64 + w0;
    for (int e = tid; e < E; e += 512) {
        int k = e >> 4, pp = e & 15;
        float oy = offA[(2*k)*4096   + pp] + offB[(2*k)*4096   + pp];
        float ox = offA[(2*k+1)*4096 + pp] + offB[(2*k+1)*4096 + pp];
        float py = (float)(h - PAD + DIL*(k/K)) + oy;
        float px = (float)(w0 + pp - PAD + DIL*(k%K)) + ox;
        float fy = floorf(py), fx = floorf(px);
        float wy1 = py - fy, wx1 = px - fx;
        int y0 = (int)fy, x0i = (int)fx;
        bool yv0 = (unsigned)y0        < 64u;
        bool yv1 = (unsigned)(y0 + 1)  < 64u;
        bool xv0 = (unsigned)x0i       < 64u;
        bool xv1 = (unsigned)(x0i + 1) < 64u;
        int yc0 = min(max(y0, 0), 63),  yc1 = min(max(y0 + 1, 0), 63);
        int xc0 = min(max(x0i, 0), 63), xc1 = min(max(x0i + 1, 0), 63);
        float wy0f = 1.f - wy1, wx0f = 1.f - wx1;
        s_i4[e] = make_int4(yc0*4096 + xc0*64, yc0*4096 + xc1*64,
                            yc1*4096 + xc0*64, yc1*4096 + xc1*64);
        float m00 = (yv0 && xv0) ? wy0f*wx0f : 0.f;
        float m01 = (yv0 && xv1) ? wy0f*wx1  : 0.f;
        float m10 = (yv1 && xv0) ? wy1 *wx0f : 0.f;
        float m11 = (yv1 && xv1) ? wy1 *wx1  : 0.f;
        s_wh[e][0] = __floats2half2_rn(m00, m00);
        s_wh[e][1] = __floats2half2_rn(m01, m01);
        s_wh[e][2] = __floats2half2_rn(m10, m10);
        s_wh[e][3] = __floats2half2_rn(m11, m11);
    }
    __syncthreads();

    // stage 2
    const __half* base = (const __half*)g_attn0T + (size_t)b*262144 + 2*tx;
    float accx = 0.f, accy = 0.f;
#pragma unroll 7
    for (int k = 0; k < K2; ++k) {
        int e = (k << 4) | p;
        int4  I = s_i4[e];
        half2 W0 = s_wh[e][0], W1 = s_wh[e][1], W2 = s_wh[e][2], W3 = s_wh[e][3];
        half2 g00 = *(const half2*)(base + I.x);
        half2 g01 = *(const half2*)(base + I.y);
        half2 g10 = *(const half2*)(base + I.z);
        half2 g11 = *(const half2*)(base + I.w);
        half2 v = __hmul2(g00, W0);
        v = __hfma2(g01, W1, v);
        v = __hfma2(g10, W2, v);
        v = __hfma2(g11, W3, v);
        float2 vf = __half22float2(v);
        float2 wd = *(const float2*)(s_wdw + k*64 + 2*tx);
        accx += vf.x * wd.x;
        accy += vf.y * wd.y;
    }
    float2 bd = *(const float2*)(bdw + 2*tx);
    accx += bd.x; accy += bd.y;

    // fused 1x1 conv (o-quad FMA2 form) + out = x * attn
    __syncthreads();
    float* s_a = (float*)&s_i4[0];       // [p][c] stride 68 (4.4 KB)
    s_a[p*68 + 2*tx]     = accx;
    s_a[p*68 + 2*tx + 1] = accy;
    __syncthreads();
    float* s_t = (float*)&s_wh[0][0];    // [p][o] stride 68 (4.4 KB)
    if (tid < 256) {
        int q  = tid & 15;               // o-quad: outputs 4q..4q+3
        int px = tid >> 4;               // pixel
        float4 bp = *(const float4*)(bpw + 4*q);
        ulonglong2 r2;
        { unsigned long long zz; PACK2(zz, 0.f); r2.x = zz; r2.y = zz; }
        const float* pwp = (const float*)g_wpwT + 4*q;
#pragma unroll 16
        for (int c = 0; c < 64; ++c) {
            float a = s_a[px*68 + c];
            unsigned long long av; PACK2(av, a);
            ulonglong2 pwv = *(const ulonglong2*)(pwp + c*64);
            FMA2(r2.x, av, pwv.x, r2.x);
            FMA2(r2.y, av, pwv.y, r2.y);
        }
        float r0, r1, r2f, r3;
        UNPACK2(r0, r1, r2.x);
        UNPACK2(r2f, r3, r2.y);
        *(float4*)(s_t + px*68 + 4*q) =
            make_float4(r0 + bp.x, r1 + bp.y, r2f + bp.z, r3 + bp.w);
    }
    __syncthreads();
    for (int v = tid; v < 1024; v += 512) {
        int c = v >> 4, pp = v & 15;
        int gi = ((b*64 + c)*64 + h)*64 + w0 + pp;
        outF[gi] = x[gi] * s_t[pp*68 + c];
    }
}

// ---------------- launch ----------------
extern "C" void kernel_launch(void* const* d_in, const int* in_sizes, int n_in,
                              void* d_out, int out_size) {
    const float* x      = (const float*)d_in[0];
    const float* w_off0 = (const float*)d_in[1];
    const float* b_off0 = (const float*)d_in[2];
    const float* w_dw0  = (const float*)d_in[3];
    const float* b_dw0  = (const float*)d_in[4];
    const float* w_off1 = (const float*)d_in[5];
    const float* b_off1 = (const float*)d_in[6];
    const float* w_dw1  = (const float*)d_in[7];
    const float* b_dw1  = (const float*)d_in[8];
    const float* w_pw   = (const float*)d_in[9];
    const float* b_pw   = (const float*)d_in[10];
    float* out = (float*)d_out;

    prep_transpose_kernel<<<256 + 225, 256>>>(x, w_off0, w_off1, w_dw0, w_dw1, w_pw);

    dim3 cb(16, 13);
    offconv_kernel<<<dim3(64, NB, 2), cb>>>(x, b_off0, 0);

    deform5_kernel<<<dim3(2, 64, NB), dim3(16, 32)>>>(b_dw0);

    offconv_kernel<<<dim3(64, NB, 4), cb>>>(x, b_off1, 1);

    deform7_kernel<<<dim3(4, 64, NB), dim3(32, 16)>>>(b_dw1, out, x, b_pw);
}

// round 12
// speedup vs baseline: 1.0281x; 1.0281x over previous
#include <cuda_runtime.h>
#include <cuda_fp16.h>
#include <cstdint>

#define NB 4
#define NC 64
#define NH 64
#define NW 64
#define NHW 4096

// ---- packed fp32x2 helpers (PTX-only; ptxas never auto-fuses) ----
#define PACK2(d, v)   asm("mov.b64 %0, {%1, %1};" : "=l"(d) : "r"(__float_as_uint(v)))
#define UNPACK2(l_, h_, in_) do { unsigned _ulo, _uhi; \
    asm("mov.b64 {%0, %1}, %2;" : "=r"(_ulo), "=r"(_uhi) : "l"(in_)); \
    l_ = __uint_as_float(_ulo); h_ = __uint_as_float(_uhi); } while (0)
#define FMA2(d, a, b, c) asm("fma.rn.f32x2 %0, %1, %2, %3;" : "=l"(d) : "l"(a), "l"(b), "l"(c))
#define MUL2(d, a, b)    asm("mul.rn.f32x2 %0, %1, %2;"     : "=l"(d) : "l"(a), "l"(b))

// ---------------- device scratch (no allocations allowed anywhere) ----------------
__device__ __align__(16) __half g_xT[NB*NHW*NC];     // x in NHWC, fp16 (gather source)
__device__ __align__(16) float g_attn0[NB*NC*NHW];   // attn after deform0, NCHW fp32
__device__ __align__(16) __half g_attn0T[NB*NHW*NC]; // attn after deform0, NHWC fp16
__device__ __align__(16) float g_off0[NB*50*NHW];
__device__ __align__(16) float g_off1[NB*98*NHW];
__device__ __align__(16) float g_wT0[576*52];        // [c*9+tap][o] padded 50->52
__device__ __align__(16) float g_wT1[576*100 + 64];  // padded 98->100 (+guard)
__device__ __align__(16) float g_wdw0T[25*64];       // [k][c]
__device__ __align__(16) float g_wdw1T[49*64];       // [k][c]
__device__ __align__(16) float g_wpwT[64*64];        // [c][o]

// ---------------- merged weight repack + NCHW->NHWC fp16 transpose ----------------
__global__ void prep_transpose_kernel(const float* __restrict__ x,
                                      const float* __restrict__ w_off0,
                                      const float* __restrict__ w_off1,
                                      const float* __restrict__ w_dw0,
                                      const float* __restrict__ w_dw1,
                                      const float* __restrict__ w_pw) {
    __shared__ float sm[64*65];
    if (blockIdx.x < 256) {
        int bh = blockIdx.x;
        int b = bh >> 6, h = bh & 63;
        int tid = threadIdx.x;
        for (int i = tid; i < 4096; i += 256) {
            int c = i >> 6, w = i & 63;
            sm[c*65 + w] = x[((b*64 + c)*64 + h)*64 + w];
        }
        __syncthreads();
        for (int i = tid; i < 4096; i += 256) {
            int w = i >> 6, c = i & 63;
            g_xT[(b*4096 + h*64 + w)*64 + c] = __float2half_rn(sm[c*65 + w]);
        }
    } else {
        int i = (blockIdx.x - 256) * 256 + threadIdx.x;
        if (i < 576*52) {
            int r = i / 52, o = i % 52, c = r / 9, t = r % 9;
            g_wT0[i] = (o < 50) ? w_off0[(o*64 + c)*9 + t] : 0.f;
        }
        if (i < 576*100) {
            int r = i / 100, o = i % 100, c = r / 9, t = r % 9;
            g_wT1[i] = (o < 98) ? w_off1[(o*64 + c)*9 + t] : 0.f;
        }
        if (i < 25*64) { int k = i >> 6, c = i & 63; g_wdw0T[i] = w_dw0[c*25 + k]; }
        if (i < 49*64) { int k = i >> 6, c = i & 63; g_wdw1T[i] = w_dw1[c*49 + k]; }
        if (i < 4096)  { int c = i >> 6, o = i & 63; g_wpwT[i]  = w_pw[o*64 + c]; }
    }
}

// ---------------- 3x3 offset conv (pad=1): smem-staged weights, 8-channel chunks ----------------
// Block (16,13): tx = 4-pixel group, ty = 4-output group. One block covers all 64 input
// channels (8 chunks of 8); weights + x-slab staged in smem so the inner loop is LDS-only.
__global__ void offconv_kernel(const float* __restrict__ xin,
                               const float* __restrict__ bias, int which) {
    __shared__ float xs[3*8*68];      // 6528 B
    __shared__ float ws[8*9*100];     // 28800 B
    const int tx = threadIdx.x, ty = threadIdx.y;
    const int tid = ty*16 + tx;       // 208 threads
    const int b = blockIdx.y, h = blockIdx.x;
    const int ogrp = blockIdx.z;
    const float* src = which ? (const float*)g_attn0 : xin;

    const float* wT = which ? (const float*)g_wT1 : (const float*)g_wT0;
    const int OPAD = which ? 100 : 52;
    const int O    = which ? 98  : 50;
    float* outp    = which ? (float*)g_off1 : (float*)g_off0;

    int o4 = ogrp*52 + ty*4;
    const bool active = (o4 + 4 <= OPAD);
    if (!active) o4 = 0;              // compute harmlessly, never store
    const int n4 = (8*9*OPAD) >> 2;   // float4 count per weight chunk

    unsigned long long acc[4][2];
    unsigned long long z; PACK2(z, 0.f);
#pragma unroll
    for (int j = 0; j < 4; ++j) { acc[j][0] = z; acc[j][1] = z; }

    for (int c0 = 0; c0 < 64; c0 += 8) {
        __syncthreads();              // protect smem from prior-chunk readers
        // stage weight chunk (contiguous in g_wT)
        {
            const float4* wsrc = (const float4*)(wT + c0*9*OPAD);
            float4* wdst = (float4*)ws;
            for (int i = tid; i < n4; i += 208) wdst[i] = wsrc[i];
        }
        // stage x slab: rows h-1..h+1, channels c0..c0+7
        for (int i = tid; i < 3*8*64; i += 208) {
            int r = i >> 9, rem = i & 511, c = rem >> 6, w = rem & 63;
            int hh = h + r - 1;
            float v = 0.f;
            if (hh >= 0 && hh < 64) v = src[((b*64 + c0 + c)*64 + hh)*64 + w];
            xs[(r*8 + c)*68 + w + 1] = v;
        }
        if (tid < 24) {
            int base = tid * 68;
            xs[base] = 0.f; xs[base+65] = 0.f; xs[base+66] = 0.f; xs[base+67] = 0.f;
        }
        __syncthreads();

        for (int c = 0; c < 8; ++c) {
            const float* xrow = xs + c*68 + 4*tx;
            const float* wrow = ws + c*9*OPAD + o4;
#pragma unroll
            for (int dy = 0; dy < 3; ++dy) {
                float4 A  = *(const float4*)(xrow + dy*(8*68));
                float2 Bv = *(const float2*)(xrow + dy*(8*68) + 4);
                float v[6] = {A.x, A.y, A.z, A.w, Bv.x, Bv.y};
                unsigned long long vv[6];
#pragma unroll
                for (int j = 0; j < 6; ++j) PACK2(vv[j], v[j]);
#pragma unroll
                for (int dx = 0; dx < 3; ++dx) {
                    ulonglong2 wv = *(const ulonglong2*)(wrow + (dy*3 + dx)*OPAD);
#pragma unroll
                    for (int j = 0; j < 4; ++j) {
                        FMA2(acc[j][0], vv[j+dx], wv.x, acc[j][0]);
                        FMA2(acc[j][1], vv[j+dx], wv.y, acc[j][1]);
                    }
                }
            }
        }
    }

    if (active) {
        float a0, a1, a2, a3;
#pragma unroll
        for (int j = 0; j < 4; ++j) {
            UNPACK2(a0, a1, acc[j][0]);
            UNPACK2(a2, a3, acc[j][1]);
            float r4[4] = {a0, a1, a2, a3};
#pragma unroll
            for (int oo = 0; oo < 4; ++oo) {
                int o = o4 + oo;
                if (o >= O) break;
                outp[((b*O + o)*64 + h)*64 + 4*tx + j] = r4[oo] + bias[o];
            }
        }
    }
}

// ---------------- deformable depthwise conv: tap precompute + fp16 gathers + HFMA2 ----------------
// Proven R10 shape: block (32,16) = 512 threads, 2 channels/thread.
template<int K, int DIL, bool FUSE>
__global__ void __launch_bounds__(512) deform_kernel(const float* __restrict__ bdw,
                                                     float* __restrict__ outF,
                                                     const float* __restrict__ x,
                                                     const float* __restrict__ bpw) {
    constexpr int K2  = K * K;
    constexpr int PAD = (K / 2) * DIL;
    constexpr int E   = K2 * 16;
    __shared__ __align__(16) int4  s_i4[E];
    __shared__ __align__(16) half2 s_wh[E][4];   // lane-duplicated bilinear weights
    __shared__ float s_wdw[K2*64];

    const int tx = threadIdx.x;          // channel pair: channels 2tx, 2tx+1
    const int p  = threadIdx.y;          // pixel within block
    const int tid = p*32 + tx;
    const int b = blockIdx.z, h = blockIdx.y, w0 = blockIdx.x * 16;

    const float* wdwT = FUSE ? (const float*)g_wdw1T : (const float*)g_wdw0T;
    for (int i = tid; i < K2*64; i += 512) s_wdw[i] = wdwT[i];

    // ---- stage 1: per (pixel, tap) clamped indices + masked half2 bilinear weights ----
    const float* offA = (FUSE ? (const float*)g_off1 : (const float*)g_off0)
                        + (size_t)(b*2*K2)*4096 + h*64 + w0;
    for (int e = tid; e < E; e += 512) {
        int k = e >> 4, pp = e & 15;
        float oy = offA[(2*k)*4096   + pp];
        float ox = offA[(2*k+1)*4096 + pp];
        float py = (float)(h - PAD + DIL*(k/K)) + oy;
        float px = (float)(w0 + pp - PAD + DIL*(k%K)) + ox;
        float fy = floorf(py), fx = floorf(px);
        float wy1 = py - fy, wx1 = px - fx;
        int y0 = (int)fy, x0i = (int)fx;
        bool yv0 = (unsigned)y0        < 64u;
        bool yv1 = (unsigned)(y0 + 1)  < 64u;
        bool xv0 = (unsigned)x0i       < 64u;
        bool xv1 = (unsigned)(x0i + 1) < 64u;
        int yc0 = min(max(y0, 0), 63),  yc1 = min(max(y0 + 1, 0), 63);
        int xc0 = min(max(x0i, 0), 63), xc1 = min(max(x0i + 1, 0), 63);
        float wy0f = 1.f - wy1, wx0f = 1.f - wx1;
        s_i4[e] = make_int4(yc0*4096 + xc0*64, yc0*4096 + xc1*64,
                            yc1*4096 + xc0*64, yc1*4096 + xc1*64);
        float m00 = (yv0 && xv0) ? wy0f*wx0f : 0.f;
        float m01 = (yv0 && xv1) ? wy0f*wx1  : 0.f;
        float m10 = (yv1 && xv0) ? wy1 *wx0f : 0.f;
        float m11 = (yv1 && xv1) ? wy1 *wx1  : 0.f;
        s_wh[e][0] = __floats2half2_rn(m00, m00);
        s_wh[e][1] = __floats2half2_rn(m01, m01);
        s_wh[e][2] = __floats2half2_rn(m10, m10);
        s_wh[e][3] = __floats2half2_rn(m11, m11);
    }
    __syncthreads();

    // ---- stage 2: fp16 gathers + HFMA2 bilinear + fp32 depthwise accumulate ----
    const __half* base = (FUSE ? (const __half*)g_attn0T : (const __half*)g_xT)
                         + (size_t)b*262144 + 2*tx;
    float accx = 0.f, accy = 0.f;
#pragma unroll 7
    for (int k = 0; k < K2; ++k) {
        int e = (k << 4) | p;
        int4  I = s_i4[e];
        half2 W0 = s_wh[e][0], W1 = s_wh[e][1], W2 = s_wh[e][2], W3 = s_wh[e][3];
        half2 g00 = *(const half2*)(base + I.x);
        half2 g01 = *(const half2*)(base + I.y);
        half2 g10 = *(const half2*)(base + I.z);
        half2 g11 = *(const half2*)(base + I.w);
        half2 v = __hmul2(g00, W0);
        v = __hfma2(g01, W1, v);
        v = __hfma2(g10, W2, v);
        v = __hfma2(g11, W3, v);
        float2 vf = __half22float2(v);
        float2 wd = *(const float2*)(s_wdw + k*64 + 2*tx);
        accx += vf.x * wd.x;
        accy += vf.y * wd.y;
    }
    float2 bd = *(const float2*)(bdw + 2*tx);
    accx += bd.x; accy += bd.y;

    if (!FUSE) {
        // NHWC fp16 store (coalesced), source for deform7
        *(half2*)(g_attn0T + (size_t)(b*4096 + h*64 + w0 + p)*64 + 2*tx) =
            __floats2half2_rn(accx, accy);
        // NCHW fp32 store via smem transpose (alias s_wh — done reading it)
        __syncthreads();
        float* s_t = (float*)&s_wh[0][0];    // [p][c] stride 68
        s_t[p*68 + 2*tx]     = accx;
        s_t[p*68 + 2*tx + 1] = accy;
        __syncthreads();
        for (int v = tid; v < 1024; v += 512) {
            int c = v >> 4, pp = v & 15;
            g_attn0[((b*64 + c)*64 + h)*64 + w0 + pp] = s_t[pp*68 + c];
        }
    } else {
        // fused 1x1 conv + out = x * attn
        __syncthreads();
        float* s_a = (float*)&s_i4[0];       // [p][c] stride 68
        s_a[p*68 + 2*tx]     = accx;
        s_a[p*68 + 2*tx + 1] = accy;
        __syncthreads();
        float2 bp = *(const float2*)(bpw + 2*tx);
        float rx = bp.x, ry = bp.y;
        const float* pwp = (const float*)g_wpwT + 2*tx;
#pragma unroll 8
        for (int c = 0; c < 64; ++c) {
            float a = s_a[p*68 + c];
            float2 pwv = *(const float2*)(pwp + c*64);
            rx += a * pwv.x;
            ry += a * pwv.y;
        }
        float* s_t = (float*)&s_wh[0][0];    // [p][o] stride 68
        s_t[p*68 + 2*tx]     = rx;
        s_t[p*68 + 2*tx + 1] = ry;
        __syncthreads();
        for (int v = tid; v < 1024; v += 512) {
            int c = v >> 4, pp = v & 15;
            int gi = ((b*64 + c)*64 + h)*64 + w0 + pp;
            outF[gi] = x[gi] * s_t[pp*68 + c];
        }
    }
}

// ---------------- launch ----------------
extern "C" void kernel_launch(void* const* d_in, const int* in_sizes, int n_in,
                              void* d_out, int out_size) {
    const float* x      = (const float*)d_in[0];
    const float* w_off0 = (const float*)d_in[1];
    const float* b_off0 = (const float*)d_in[2];
    const float* w_dw0  = (const float*)d_in[3];
    const float* b_dw0  = (const float*)d_in[4];
    const float* w_off1 = (const float*)d_in[5];
    const float* b_off1 = (const float*)d_in[6];
    const float* w_dw1  = (const float*)d_in[7];
    const float* b_dw1  = (const float*)d_in[8];
    const float* w_pw   = (const float*)d_in[9];
    const float* b_pw   = (const float*)d_in[10];
    float* out = (float*)d_out;

    prep_transpose_kernel<<<256 + 225, 256>>>(x, w_off0, w_off1, w_dw0, w_dw1, w_pw);

    dim3 cb(16, 13);
    offconv_kernel<<<dim3(64, NB, 1), cb>>>(x, b_off0, 0);

    deform_kernel<5, 1, false><<<dim3(4, 64, NB), dim3(32, 16)>>>(b_dw0, nullptr, nullptr, nullptr);

    offconv_kernel<<<dim3(64, NB, 2), cb>>>(x, b_off1, 1);

    deform_kernel<7, 3, true><<<dim3(4, 64, NB), dim3(32, 16)>>>(b_dw1, out, x, b_pw);
}

// round 13
// speedup vs baseline: 1.0635x; 1.0344x over previous
#include <cuda_runtime.h>
#include <cuda_fp16.h>
#include <cstdint>

#define NB 4
#define NC 64
#define NH 64
#define NW 64
#define NHW 4096

// ---- packed fp32x2 helpers (PTX-only; ptxas never auto-fuses) ----
#define PACK2(d, v)   asm("mov.b64 %0, {%1, %1};" : "=l"(d) : "r"(__float_as_uint(v)))
#define UNPACK2(l_, h_, in_) do { unsigned _ulo, _uhi; \
    asm("mov.b64 {%0, %1}, %2;" : "=r"(_ulo), "=r"(_uhi) : "l"(in_)); \
    l_ = __uint_as_float(_ulo); h_ = __uint_as_float(_uhi); } while (0)
#define FMA2(d, a, b, c) asm("fma.rn.f32x2 %0, %1, %2, %3;" : "=l"(d) : "l"(a), "l"(b), "l"(c))
#define MUL2(d, a, b)    asm("mul.rn.f32x2 %0, %1, %2;"     : "=l"(d) : "l"(a), "l"(b))

// ---------------- device scratch (no allocations allowed anywhere) ----------------
__device__ __align__(16) __half g_xT[NB*NHW*NC];     // x in NHWC, fp16 (gather source)
__device__ __align__(16) float g_attn0[NB*NC*NHW];   // attn after deform0, NCHW fp32
__device__ __align__(16) __half g_attn0T[NB*NHW*NC]; // attn after deform0, NHWC fp16
__device__ __align__(16) float g_off0[NB*50*NHW];
__device__ __align__(16) float g_off1[NB*98*NHW];
__device__ __align__(16) float g_wT0[576*52];        // [c*9+tap][o] padded 50->52
__device__ __align__(16) float g_wT1[576*104];       // [c*9+tap][o] padded 98->104
__device__ __align__(16) float g_wdw0T[25*64];       // [k][c]
__device__ __align__(16) float g_wdw1T[49*64];       // [k][c]
__device__ __align__(16) float g_wpwT[64*64];        // [c][o]

// ---------------- merged weight repack + NCHW->NHWC fp16 transpose ----------------
__global__ void prep_transpose_kernel(const float* __restrict__ x,
                                      const float* __restrict__ w_off0,
                                      const float* __restrict__ w_off1,
                                      const float* __restrict__ w_dw0,
                                      const float* __restrict__ w_dw1,
                                      const float* __restrict__ w_pw) {
    __shared__ float sm[64*65];
    if (blockIdx.x < 256) {
        int bh = blockIdx.x;
        int b = bh >> 6, h = bh & 63;
        int tid = threadIdx.x;
        for (int i = tid; i < 4096; i += 256) {
            int c = i >> 6, w = i & 63;
            sm[c*65 + w] = x[((b*64 + c)*64 + h)*64 + w];
        }
        __syncthreads();
        for (int i = tid; i < 4096; i += 256) {
            int w = i >> 6, c = i & 63;
            g_xT[(b*4096 + h*64 + w)*64 + c] = __float2half_rn(sm[c*65 + w]);
        }
    } else {
        int i = (blockIdx.x - 256) * 256 + threadIdx.x;
        if (i < 576*52) {
            int r = i / 52, o = i % 52, c = r / 9, t = r % 9;
            g_wT0[i] = (o < 50) ? w_off0[(o*64 + c)*9 + t] : 0.f;
        }
        if (i < 576*104) {
            int r = i / 104, o = i % 104, c = r / 9, t = r % 9;
            g_wT1[i] = (o < 98) ? w_off1[(o*64 + c)*9 + t] : 0.f;
        }
        if (i < 25*64) { int k = i >> 6, c = i & 63; g_wdw0T[i] = w_dw0[c*25 + k]; }
        if (i < 49*64) { int k = i >> 6, c = i & 63; g_wdw1T[i] = w_dw1[c*49 + k]; }
        if (i < 4096)  { int c = i >> 6, o = i & 63; g_wpwT[i]  = w_pw[o*64 + c]; }
    }
}

// ---------------- conv0: 3x3, 64->50, smem-staged, 4 outputs/thread (R12 proven) ----------------
__global__ void offconv0_kernel(const float* __restrict__ xin,
                                const float* __restrict__ bias) {
    constexpr int OPAD = 52, O = 50;
    __shared__ float xs[3*8*68];      // 6528 B
    __shared__ float ws[8*9*OPAD];    // 14976 B
    const int tx = threadIdx.x, ty = threadIdx.y;
    const int tid = ty*16 + tx;       // 208 threads
    const int b = blockIdx.y, h = blockIdx.x;
    const int o4 = ty*4;
    const int n4 = (8*9*OPAD) >> 2;

    unsigned long long acc[4][2];
    unsigned long long z; PACK2(z, 0.f);
#pragma unroll
    for (int j = 0; j < 4; ++j) { acc[j][0] = z; acc[j][1] = z; }

    for (int c0 = 0; c0 < 64; c0 += 8) {
        __syncthreads();
        {
            const float4* wsrc = (const float4*)(g_wT0 + c0*9*OPAD);
            float4* wdst = (float4*)ws;
            for (int i = tid; i < n4; i += 208) wdst[i] = wsrc[i];
        }
        for (int i = tid; i < 3*8*64; i += 208) {
            int r = i >> 9, rem = i & 511, c = rem >> 6, w = rem & 63;
            int hh = h + r - 1;
            float v = 0.f;
            if (hh >= 0 && hh < 64) v = xin[((b*64 + c0 + c)*64 + hh)*64 + w];
            xs[(r*8 + c)*68 + w + 1] = v;
        }
        if (tid < 24) {
            int base = tid * 68;
            xs[base] = 0.f; xs[base+65] = 0.f; xs[base+66] = 0.f; xs[base+67] = 0.f;
        }
        __syncthreads();

        for (int c = 0; c < 8; ++c) {
            const float* xrow = xs + c*68 + 4*tx;
            const float* wrow = ws + c*9*OPAD + o4;
#pragma unroll
            for (int dy = 0; dy < 3; ++dy) {
                float4 A  = *(const float4*)(xrow + dy*(8*68));
                float2 Bv = *(const float2*)(xrow + dy*(8*68) + 4);
                float v[6] = {A.x, A.y, A.z, A.w, Bv.x, Bv.y};
                unsigned long long vv[6];
#pragma unroll
                for (int j = 0; j < 6; ++j) PACK2(vv[j], v[j]);
#pragma unroll
                for (int dx = 0; dx < 3; ++dx) {
                    ulonglong2 wv = *(const ulonglong2*)(wrow + (dy*3 + dx)*OPAD);
#pragma unroll
                    for (int j = 0; j < 4; ++j) {
                        FMA2(acc[j][0], vv[j+dx], wv.x, acc[j][0]);
                        FMA2(acc[j][1], vv[j+dx], wv.y, acc[j][1]);
                    }
                }
            }
        }
    }

    float a0, a1, a2, a3;
#pragma unroll
    for (int j = 0; j < 4; ++j) {
        UNPACK2(a0, a1, acc[j][0]);
        UNPACK2(a2, a3, acc[j][1]);
        float r4[4] = {a0, a1, a2, a3};
#pragma unroll
        for (int oo = 0; oo < 4; ++oo) {
            int o = o4 + oo;
            if (o >= O) break;
            g_off0[((b*O + o)*64 + h)*64 + 4*tx + j] = r4[oo] + bias[o];
        }
    }
}

// ---------------- conv1: 3x3, 64->98, smem-staged, 8 outputs/thread ----------------
// ty*8 covers all 104 padded outputs in one block per (b,h): no duplicate staging.
__global__ void offconv1_kernel(const float* __restrict__ bias) {
    constexpr int OPAD = 104, O = 98;
    __shared__ float xs[3*8*68];      // 6528 B
    __shared__ float ws[8*9*OPAD];    // 29952 B
    const int tx = threadIdx.x, ty = threadIdx.y;
    const int tid = ty*16 + tx;       // 208 threads
    const int b = blockIdx.y, h = blockIdx.x;
    const int o8 = ty*8;
    const int n4 = (8*9*OPAD) >> 2;   // 1872

    unsigned long long acc[4][4];     // [pixel j][o-pair]
    unsigned long long z; PACK2(z, 0.f);
#pragma unroll
    for (int j = 0; j < 4; ++j)
#pragma unroll
        for (int q = 0; q < 4; ++q) acc[j][q] = z;

    for (int c0 = 0; c0 < 64; c0 += 8) {
        __syncthreads();
        {
            const float4* wsrc = (const float4*)(g_wT1 + c0*9*OPAD);
            float4* wdst = (float4*)ws;
            for (int i = tid; i < n4; i += 208) wdst[i] = wsrc[i];
        }
        for (int i = tid; i < 3*8*64; i += 208) {
            int r = i >> 9, rem = i & 511, c = rem >> 6, w = rem & 63;
            int hh = h + r - 1;
            float v = 0.f;
            if (hh >= 0 && hh < 64) v = g_attn0[((b*64 + c0 + c)*64 + hh)*64 + w];
            xs[(r*8 + c)*68 + w + 1] = v;
        }
        if (tid < 24) {
            int base = tid * 68;
            xs[base] = 0.f; xs[base+65] = 0.f; xs[base+66] = 0.f; xs[base+67] = 0.f;
        }
        __syncthreads();

        for (int c = 0; c < 8; ++c) {
            const float* xrow = xs + c*68 + 4*tx;
            const float* wrow = ws + c*9*OPAD + o8;
#pragma unroll
            for (int dy = 0; dy < 3; ++dy) {
                float4 A  = *(const float4*)(xrow + dy*(8*68));
                float2 Bv = *(const float2*)(xrow + dy*(8*68) + 4);
                float v[6] = {A.x, A.y, A.z, A.w, Bv.x, Bv.y};
                unsigned long long vv[6];
#pragma unroll
                for (int j = 0; j < 6; ++j) PACK2(vv[j], v[j]);
#pragma unroll
                for (int dx = 0; dx < 3; ++dx) {
                    ulonglong2 w01 = *(const ulonglong2*)(wrow + (dy*3 + dx)*OPAD);
                    ulonglong2 w23 = *(const ulonglong2*)(wrow + (dy*3 + dx)*OPAD + 4);
#pragma unroll
                    for (int j = 0; j < 4; ++j) {
                        FMA2(acc[j][0], vv[j+dx], w01.x, acc[j][0]);
                        FMA2(acc[j][1], vv[j+dx], w01.y, acc[j][1]);
                        FMA2(acc[j][2], vv[j+dx], w23.x, acc[j][2]);
                        FMA2(acc[j][3], vv[j+dx], w23.y, acc[j][3]);
                    }
                }
            }
        }
    }

#pragma unroll
    for (int j = 0; j < 4; ++j) {
        float r8[8];
        UNPACK2(r8[0], r8[1], acc[j][0]);
        UNPACK2(r8[2], r8[3], acc[j][1]);
        UNPACK2(r8[4], r8[5], acc[j][2]);
        UNPACK2(r8[6], r8[7], acc[j][3]);
#pragma unroll
        for (int oo = 0; oo < 8; ++oo) {
            int o = o8 + oo;
            if (o < O)
                g_off1[((b*O + o)*64 + h)*64 + 4*tx + j] = r8[oo] + bias[o];
        }
    }
}

// ---------------- deformable depthwise conv: tap precompute + fp16 gathers + HFMA2 ----------------
// Proven R10/R12 shape: block (32,16) = 512 threads, 2 channels/thread.
template<int K, int DIL, bool FUSE>
__global__ void __launch_bounds__(512) deform_kernel(const float* __restrict__ bdw,
                                                     float* __restrict__ outF,
                                                     const float* __restrict__ x,
                                                     const float* __restrict__ bpw) {
    constexpr int K2  = K * K;
    constexpr int PAD = (K / 2) * DIL;
    constexpr int E   = K2 * 16;
    __shared__ __align__(16) int4  s_i4[E];
    __shared__ __align__(16) half2 s_wh[E][4];   // lane-duplicated bilinear weights
    __shared__ float s_wdw[K2*64];

    const int tx = threadIdx.x;          // channel pair: channels 2tx, 2tx+1
    const int p  = threadIdx.y;          // pixel within block
    const int tid = p*32 + tx;
    const int b = blockIdx.z, h = blockIdx.y, w0 = blockIdx.x * 16;

    const float* wdwT = FUSE ? (const float*)g_wdw1T : (const float*)g_wdw0T;
    for (int i = tid; i < K2*64; i += 512) s_wdw[i] = wdwT[i];

    const float* offA = (FUSE ? (const float*)g_off1 : (const float*)g_off0)
                        + (size_t)(b*2*K2)*4096 + h*64 + w0;
    for (int e = tid; e < E; e += 512) {
        int k = e >> 4, pp = e & 15;
        float oy = offA[(2*k)*4096   + pp];
        float ox = offA[(2*k+1)*4096 + pp];
        float py = (float)(h - PAD + DIL*(k/K)) + oy;
        float px = (float)(w0 + pp - PAD + DIL*(k%K)) + ox;
        float fy = floorf(py), fx = floorf(px);
        float wy1 = py - fy, wx1 = px - fx;
        int y0 = (int)fy, x0i = (int)fx;
        bool yv0 = (unsigned)y0        < 64u;
        bool yv1 = (unsigned)(y0 + 1)  < 64u;
        bool xv0 = (unsigned)x0i       < 64u;
        bool xv1 = (unsigned)(x0i + 1) < 64u;
        int yc0 = min(max(y0, 0), 63),  yc1 = min(max(y0 + 1, 0), 63);
        int xc0 = min(max(x0i, 0), 63), xc1 = min(max(x0i + 1, 0), 63);
        float wy0f = 1.f - wy1, wx0f = 1.f - wx1;
        s_i4[e] = make_int4(yc0*4096 + xc0*64, yc0*4096 + xc1*64,
                            yc1*4096 + xc0*64, yc1*4096 + xc1*64);
        float m00 = (yv0 && xv0) ? wy0f*wx0f : 0.f;
        float m01 = (yv0 && xv1) ? wy0f*wx1  : 0.f;
        float m10 = (yv1 && xv0) ? wy1 *wx0f : 0.f;
        float m11 = (yv1 && xv1) ? wy1 *wx1  : 0.f;
        s_wh[e][0] = __floats2half2_rn(m00, m00);
        s_wh[e][1] = __floats2half2_rn(m01, m01);
        s_wh[e][2] = __floats2half2_rn(m10, m10);
        s_wh[e][3] = __floats2half2_rn(m11, m11);
    }
    __syncthreads();

    const __half* base = (FUSE ? (const __half*)g_attn0T : (const __half*)g_xT)
                         + (size_t)b*262144 + 2*tx;
    float accx = 0.f, accy = 0.f;
#pragma unroll 7
    for (int k = 0; k < K2; ++k) {
        int e = (k << 4) | p;
        int4  I = s_i4[e];
        half2 W0 = s_wh[e][0], W1 = s_wh[e][1], W2 = s_wh[e][2], W3 = s_wh[e][3];
        half2 g00 = *(const half2*)(base + I.x);
        half2 g01 = *(const half2*)(base + I.y);
        half2 g10 = *(const half2*)(base + I.z);
        half2 g11 = *(const half2*)(base + I.w);
        half2 v = __hmul2(g00, W0);
        v = __hfma2(g01, W1, v);
        v = __hfma2(g10, W2, v);
        v = __hfma2(g11, W3, v);
        float2 vf = __half22float2(v);
        float2 wd = *(const float2*)(s_wdw + k*64 + 2*tx);
        accx += vf.x * wd.x;
        accy += vf.y * wd.y;
    }
    float2 bd = *(const float2*)(bdw + 2*tx);
    accx += bd.x; accy += bd.y;

    if (!FUSE) {
        *(half2*)(g_attn0T + (size_t)(b*4096 + h*64 + w0 + p)*64 + 2*tx) =
            __floats2half2_rn(accx, accy);
        __syncthreads();
        float* s_t = (float*)&s_wh[0][0];    // [p][c] stride 68
        s_t[p*68 + 2*tx]     = accx;
        s_t[p*68 + 2*tx + 1] = accy;
        __syncthreads();
        for (int v = tid; v < 1024; v += 512) {
            int c = v >> 4, pp = v & 15;
            g_attn0[((b*64 + c)*64 + h)*64 + w0 + pp] = s_t[pp*68 + c];
        }
    } else {
        __syncthreads();
        float* s_a = (float*)&s_i4[0];       // [p][c] stride 68
        s_a[p*68 + 2*tx]     = accx;
        s_a[p*68 + 2*tx + 1] = accy;
        __syncthreads();
        float2 bp = *(const float2*)(bpw + 2*tx);
        float rx = bp.x, ry = bp.y;
        const float* pwp = (const float*)g_wpwT + 2*tx;
#pragma unroll 8
        for (int c = 0; c < 64; ++c) {
            float a = s_a[p*68 + c];
            float2 pwv = *(const float2*)(pwp + c*64);
            rx += a * pwv.x;
            ry += a * pwv.y;
        }
        float* s_t = (float*)&s_wh[0][0];    // [p][o] stride 68
        s_t[p*68 + 2*tx]     = rx;
        s_t[p*68 + 2*tx + 1] = ry;
        __syncthreads();
        for (int v = tid; v < 1024; v += 512) {
            int c = v >> 4, pp = v & 15;
            int gi = ((b*64 + c)*64 + h)*64 + w0 + pp;
            outF[gi] = x[gi] * s_t[pp*68 + c];
        }
    }
}

// ---------------- launch ----------------
extern "C" void kernel_launch(void* const* d_in, const int* in_sizes, int n_in,
                              void* d_out, int out_size) {
    const float* x      = (const float*)d_in[0];
    const float* w_off0 = (const float*)d_in[1];
    const float* b_off0 = (const float*)d_in[2];
    const float* w_dw0  = (const float*)d_in[3];
    const float* b_dw0  = (const float*)d_in[4];
    const float* w_off1 = (const float*)d_in[5];
    const float* b_off1 = (const float*)d_in[6];
    const float* w_dw1  = (const float*)d_in[7];
    const float* b_dw1  = (const float*)d_in[8];
    const float* w_pw   = (const float*)d_in[9];
    const float* b_pw   = (const float*)d_in[10];
    float* out = (float*)d_out;

    prep_transpose_kernel<<<256 + 234, 256>>>(x, w_off0, w_off1, w_dw0, w_dw1, w_pw);

    dim3 cb(16, 13);
    offconv0_kernel<<<dim3(64, NB), cb>>>(x, b_off0);

    deform_kernel<5, 1, false><<<dim3(4, 64, NB), dim3(32, 16)>>>(b_dw0, nullptr, nullptr, nullptr);

    offconv1_kernel<<<dim3(64, NB), cb>>>(b_off1);

    deform_kernel<7, 3, true><<<dim3(4, 64, NB), dim3(32, 16)>>>(b_dw1, out, x, b_pw);
}

// round 15
// speedup vs baseline: 1.1109x; 1.0446x over previous
#include <cuda_runtime.h>
#include <cuda_fp16.h>
#include <cstdint>

#define NB 4
#define NC 64
#define NH 64
#define NW 64
#define NHW 4096

// ---- packed fp32x2 helpers (PTX-only; ptxas never auto-fuses) ----
#define PACK2(d, v)   asm("mov.b64 %0, {%1, %1};" : "=l"(d) : "r"(__float_as_uint(v)))
#define UNPACK2(l_, h_, in_) do { unsigned _ulo, _uhi; \
    asm("mov.b64 {%0, %1}, %2;" : "=r"(_ulo), "=r"(_uhi) : "l"(in_)); \
    l_ = __uint_as_float(_ulo); h_ = __uint_as_float(_uhi); } while (0)
#define FMA2(d, a, b, c) asm("fma.rn.f32x2 %0, %1, %2, %3;" : "=l"(d) : "l"(a), "l"(b), "l"(c))
#define MUL2(d, a, b)    asm("mul.rn.f32x2 %0, %1, %2;"     : "=l"(d) : "l"(a), "l"(b))

// ---------------- device scratch (no allocations allowed anywhere) ----------------
__device__ __align__(16) __half g_xT[NB*NHW*NC];     // x in NHWC, fp16 (gather source)
__device__ __align__(16) float g_attn0[NB*NC*NHW];   // attn after deform0, NCHW fp32
__device__ __align__(16) __half g_attn0T[NB*NHW*NC]; // attn after deform0, NHWC fp16
__device__ __align__(16) float g_off0 [NB*50*NHW];   // partial c0..31 (+bias)
__device__ __align__(16) float g_off0b[NB*50*NHW];   // partial c32..63
__device__ __align__(16) float g_off1 [NB*98*NHW];
__device__ __align__(16) float g_off1b[NB*98*NHW];
__device__ __align__(16) float g_wT0[576*52];        // [c*9+tap][o] padded 50->52
__device__ __align__(16) float g_wT1[576*104];       // [c*9+tap][o] padded 98->104
__device__ __align__(16) float g_wdw0T[25*64];       // [k][c]
__device__ __align__(16) float g_wdw1T[49*64];       // [k][c]
__device__ __align__(16) float g_wpwT[64*64];        // [c][o]

// ---------------- merged weight repack + NCHW->NHWC fp16 transpose ----------------
__global__ void prep_transpose_kernel(const float* __restrict__ x,
                                      const float* __restrict__ w_off0,
                                      const float* __restrict__ w_off1,
                                      const float* __restrict__ w_dw0,
                                      const float* __restrict__ w_dw1,
                                      const float* __restrict__ w_pw) {
    __shared__ float sm[64*65];
    if (blockIdx.x < 256) {
        int bh = blockIdx.x;
        int b = bh >> 6, h = bh & 63;
        int tid = threadIdx.x;
        for (int i = tid; i < 4096; i += 256) {
            int c = i >> 6, w = i & 63;
            sm[c*65 + w] = x[((b*64 + c)*64 + h)*64 + w];
        }
        __syncthreads();
        for (int i = tid; i < 4096; i += 256) {
            int w = i >> 6, c = i & 63;
            g_xT[(b*4096 + h*64 + w)*64 + c] = __float2half_rn(sm[c*65 + w]);
        }
    } else {
        int i = (blockIdx.x - 256) * 256 + threadIdx.x;
        if (i < 576*52) {
            int r = i / 52, o = i % 52, c = r / 9, t = r % 9;
            g_wT0[i] = (o < 50) ? w_off0[(o*64 + c)*9 + t] : 0.f;
        }
        if (i < 576*104) {
            int r = i / 104, o = i % 104, c = r / 9, t = r % 9;
            g_wT1[i] = (o < 98) ? w_off1[(o*64 + c)*9 + t] : 0.f;
        }
        if (i < 25*64) { int k = i >> 6, c = i & 63; g_wdw0T[i] = w_dw0[c*25 + k]; }
        if (i < 49*64) { int k = i >> 6, c = i & 63; g_wdw1T[i] = w_dw1[c*49 + k]; }
        if (i < 4096)  { int c = i >> 6, o = i & 63; g_wpwT[i]  = w_pw[o*64 + c]; }
    }
}

// ---------------- conv0: 3x3, 64->50, smem-staged, split-C, 4 outputs/thread ----------------
__global__ void offconv0_kernel(const float* __restrict__ xin,
                                const float* __restrict__ bias) {
    constexpr int OPAD = 52, O = 50;
    __shared__ float xs[3*8*68];      // 6528 B
    __shared__ float ws[8*9*OPAD];    // 14976 B
    const int tx = threadIdx.x, ty = threadIdx.y;
    const int tid = ty*16 + tx;       // 208 threads
    const int b = blockIdx.y, h = blockIdx.x;
    const int half_ = blockIdx.z;     // 0: c 0..31 (+bias), 1: c 32..63
    float* outp = half_ ? (float*)g_off0b : (float*)g_off0;
    const int o4 = ty*4;
    const int n4 = (8*9*OPAD) >> 2;

    unsigned long long acc[4][2];
    unsigned long long z; PACK2(z, 0.f);
#pragma unroll
    for (int j = 0; j < 4; ++j) { acc[j][0] = z; acc[j][1] = z; }

    for (int cc = 0; cc < 32; cc += 8) {
        const int c0 = half_*32 + cc;
        __syncthreads();
        {
            const float4* wsrc = (const float4*)(g_wT0 + c0*9*OPAD);
            float4* wdst = (float4*)ws;
            for (int i = tid; i < n4; i += 208) wdst[i] = wsrc[i];
        }
        for (int i = tid; i < 3*8*64; i += 208) {
            int r = i >> 9, rem = i & 511, c = rem >> 6, w = rem & 63;
            int hh = h + r - 1;
            float v = 0.f;
            if (hh >= 0 && hh < 64) v = xin[((b*64 + c0 + c)*64 + hh)*64 + w];
            xs[(r*8 + c)*68 + w + 1] = v;
        }
        if (tid < 24) {
            int base = tid * 68;
            xs[base] = 0.f; xs[base+65] = 0.f; xs[base+66] = 0.f; xs[base+67] = 0.f;
        }
        __syncthreads();

        for (int c = 0; c < 8; ++c) {
            const float* xrow = xs + c*68 + 4*tx;
            const float* wrow = ws + c*9*OPAD + o4;
#pragma unroll
            for (int dy = 0; dy < 3; ++dy) {
                float4 A  = *(const float4*)(xrow + dy*(8*68));
                float2 Bv = *(const float2*)(xrow + dy*(8*68) + 4);
                float v[6] = {A.x, A.y, A.z, A.w, Bv.x, Bv.y};
                unsigned long long vv[6];
#pragma unroll
                for (int j = 0; j < 6; ++j) PACK2(vv[j], v[j]);
#pragma unroll
                for (int dx = 0; dx < 3; ++dx) {
                    ulonglong2 wv = *(const ulonglong2*)(wrow + (dy*3 + dx)*OPAD);
#pragma unroll
                    for (int j = 0; j < 4; ++j) {
                        FMA2(acc[j][0], vv[j+dx], wv.x, acc[j][0]);
                        FMA2(acc[j][1], vv[j+dx], wv.y, acc[j][1]);
                    }
                }
            }
        }
    }

    float a0, a1, a2, a3;
#pragma unroll
    for (int j = 0; j < 4; ++j) {
        UNPACK2(a0, a1, acc[j][0]);
        UNPACK2(a2, a3, acc[j][1]);
        float r4[4] = {a0, a1, a2, a3};
#pragma unroll
        for (int oo = 0; oo < 4; ++oo) {
            int o = o4 + oo;
            if (o >= O) break;
            float bb = half_ ? 0.f : bias[o];
            outp[((b*O + o)*64 + h)*64 + 4*tx + j] = r4[oo] + bb;
        }
    }
}

// ---------------- conv1: 3x3, 64->98, smem-staged, split-C, 8 outputs/thread ----------------
__global__ void offconv1_kernel(const float* __restrict__ bias) {
    constexpr int OPAD = 104, O = 98;
    __shared__ float xs[3*8*68];      // 6528 B
    __shared__ float ws[8*9*OPAD];    // 29952 B
    const int tx = threadIdx.x, ty = threadIdx.y;
    const int tid = ty*16 + tx;       // 208 threads
    const int b = blockIdx.y, h = blockIdx.x;
    const int half_ = blockIdx.z;
    float* outp = half_ ? (float*)g_off1b : (float*)g_off1;
    const int o8 = ty*8;
    const int n4 = (8*9*OPAD) >> 2;   // 1872

    unsigned long long acc[4][4];     // [pixel j][o-pair]
    unsigned long long z; PACK2(z, 0.f);
#pragma unroll
    for (int j = 0; j < 4; ++j)
#pragma unroll
        for (int q = 0; q < 4; ++q) acc[j][q] = z;

    for (int cc = 0; cc < 32; cc += 8) {
        const int c0 = half_*32 + cc;
        __syncthreads();
        {
            const float4* wsrc = (const float4*)(g_wT1 + c0*9*OPAD);
            float4* wdst = (float4*)ws;
            for (int i = tid; i < n4; i += 208) wdst[i] = wsrc[i];
        }
        for (int i = tid; i < 3*8*64; i += 208) {
            int r = i >> 9, rem = i & 511, c = rem >> 6, w = rem & 63;
            int hh = h + r - 1;
            float v = 0.f;
            if (hh >= 0 && hh < 64) v = g_attn0[((b*64 + c0 + c)*64 + hh)*64 + w];
            xs[(r*8 + c)*68 + w + 1] = v;
        }
        if (tid < 24) {
            int base = tid * 68;
            xs[base] = 0.f; xs[base+65] = 0.f; xs[base+66] = 0.f; xs[base+67] = 0.f;
        }
        __syncthreads();

        for (int c = 0; c < 8; ++c) {
            const float* xrow = xs + c*68 + 4*tx;
            const float* wrow = ws + c*9*OPAD + o8;
#pragma unroll
            for (int dy = 0; dy < 3; ++dy) {
                float4 A  = *(const float4*)(xrow + dy*(8*68));
                float2 Bv = *(const float2*)(xrow + dy*(8*68) + 4);
                float v[6] = {A.x, A.y, A.z, A.w, Bv.x, Bv.y};
                unsigned long long vv[6];
#pragma unroll
                for (int j = 0; j < 6; ++j) PACK2(vv[j], v[j]);
#pragma unroll
                for (int dx = 0; dx < 3; ++dx) {
                    ulonglong2 w01 = *(const ulonglong2*)(wrow + (dy*3 + dx)*OPAD);
                    ulonglong2 w23 = *(const ulonglong2*)(wrow + (dy*3 + dx)*OPAD + 4);
#pragma unroll
                    for (int j = 0; j < 4; ++j) {
                        FMA2(acc[j][0], vv[j+dx], w01.x, acc[j][0]);
                        FMA2(acc[j][1], vv[j+dx], w01.y, acc[j][1]);
                        FMA2(acc[j][2], vv[j+dx], w23.x, acc[j][2]);
                        FMA2(acc[j][3], vv[j+dx], w23.y, acc[j][3]);
                    }
                }
            }
        }
    }

#pragma unroll
    for (int j = 0; j < 4; ++j) {
        float r8[8];
        UNPACK2(r8[0], r8[1], acc[j][0]);
        UNPACK2(r8[2], r8[3], acc[j][1]);
        UNPACK2(r8[4], r8[5], acc[j][2]);
        UNPACK2(r8[6], r8[7], acc[j][3]);
#pragma unroll
        for (int oo = 0; oo < 8; ++oo) {
            int o = o8 + oo;
            if (o < O) {
                float bb = half_ ? 0.f : bias[o];
                outp[((b*O + o)*64 + h)*64 + 4*tx + j] = r8[oo] + bb;
            }
        }
    }
}

// ---------------- deformable depthwise conv: tap precompute + fp16 gathers + HFMA2 ----------------
// Proven shape: block (32,16) = 512 threads, 2 channels/thread. Offsets = A + B partials.
template<int K, int DIL, bool FUSE>
__global__ void __launch_bounds__(512) deform_kernel(const float* __restrict__ bdw,
                                                     float* __restrict__ outF,
                                                     const float* __restrict__ x,
                                                     const float* __restrict__ bpw) {
    constexpr int K2  = K * K;
    constexpr int PAD = (K / 2) * DIL;
    constexpr int E   = K2 * 16;
    __shared__ __align__(16) int4  s_i4[E];
    __shared__ __align__(16) half2 s_wh[E][4];   // lane-duplicated bilinear weights
    __shared__ float s_wdw[K2*64];

    const int tx = threadIdx.x;          // channel pair: channels 2tx, 2tx+1
    const int p  = threadIdx.y;          // pixel within block
    const int tid = p*32 + tx;
    const int b = blockIdx.z, h = blockIdx.y, w0 = blockIdx.x * 16;

    const float* wdwT = FUSE ? (const float*)g_wdw1T : (const float*)g_wdw0T;
    for (int i = tid; i < K2*64; i += 512) s_wdw[i] = wdwT[i];

    const float* offA = (FUSE ? (const float*)g_off1  : (const float*)g_off0 )
                        + (size_t)(b*2*K2)*4096 + h*64 + w0;
    const float* offB = (FUSE ? (const float*)g_off1b : (const float*)g_off0b)
                        + (size_t)(b*2*K2)*4096 + h*64 + w0;
    for (int e = tid; e < E; e += 512) {
        int k = e >> 4, pp = e & 15;
        float oy = offA[(2*k)*4096   + pp] + offB[(2*k)*4096   + pp];
        float ox = offA[(2*k+1)*4096 + pp] + offB[(2*k+1)*4096 + pp];
        float py = (float)(h - PAD + DIL*(k/K)) + oy;
        float px = (float)(w0 + pp - PAD + DIL*(k%K)) + ox;
        float fy = floorf(py), fx = floorf(px);
        float wy1 = py - fy, wx1 = px - fx;
        int y0 = (int)fy, x0i = (int)fx;
        bool yv0 = (unsigned)y0        < 64u;
        bool yv1 = (unsigned)(y0 + 1)  < 64u;
        bool xv0 = (unsigned)x0i       < 64u;
        bool xv1 = (unsigned)(x0i + 1) < 64u;
        int yc0 = min(max(y0, 0), 63),  yc1 = min(max(y0 + 1, 0), 63);
        int xc0 = min(max(x0i, 0), 63), xc1 = min(max(x0i + 1, 0), 63);
        float wy0f = 1.f - wy1, wx0f = 1.f - wx1;
        s_i4[e] = make_int4(yc0*4096 + xc0*64, yc0*4096 + xc1*64,
                            yc1*4096 + xc0*64, yc1*4096 + xc1*64);
        float m00 = (yv0 && xv0) ? wy0f*wx0f : 0.f;
        float m01 = (yv0 && xv1) ? wy0f*wx1  : 0.f;
        float m10 = (yv1 && xv0) ? wy1 *wx0f : 0.f;
        float m11 = (yv1 && xv1) ? wy1 *wx1  : 0.f;
        s_wh[e][0] = __floats2half2_rn(m00, m00);
        s_wh[e][1] = __floats2half2_rn(m01, m01);
        s_wh[e][2] = __floats2half2_rn(m10, m10);
        s_wh[e][3] = __floats2half2_rn(m11, m11);
    }
    __syncthreads();

    const __half* base = (FUSE ? (const __half*)g_attn0T : (const __half*)g_xT)
                         + (size_t)b*262144 + 2*tx;
    float accx = 0.f, accy = 0.f;
#pragma unroll 7
    for (int k = 0; k < K2; ++k) {
        int e = (k << 4) | p;
        int4  I = s_i4[e];
        half2 W0 = s_wh[e][0], W1 = s_wh[e][1], W2 = s_wh[e][2], W3 = s_wh[e][3];
        half2 g00 = *(const half2*)(base + I.x);
        half2 g01 = *(const half2*)(base + I.y);
        half2 g10 = *(const half2*)(base + I.z);
        half2 g11 = *(const half2*)(base + I.w);
        half2 v = __hmul2(g00, W0);
        v = __hfma2(g01, W1, v);
        v = __hfma2(g10, W2, v);
        v = __hfma2(g11, W3, v);
        float2 vf = __half22float2(v);
        float2 wd = *(const float2*)(s_wdw + k*64 + 2*tx);
        accx += vf.x * wd.x;
        accy += vf.y * wd.y;
    }
    float2 bd = *(const float2*)(bdw + 2*tx);
    accx += bd.x; accy += bd.y;

    if (!FUSE) {
        *(half2*)(g_attn0T + (size_t)(b*4096 + h*64 + w0 + p)*64 + 2*tx) =
            __floats2half2_rn(accx, accy);
        __syncthreads();
        float* s_t = (float*)&s_wh[0][0];    // [p][c] stride 68
        s_t[p*68 + 2*tx]     = accx;
        s_t[p*68 + 2*tx + 1] = accy;
        __syncthreads();
        for (int v = tid; v < 1024; v += 512) {
            int c = v >> 4, pp = v & 15;
            g_attn0[((b*64 + c)*64 + h)*64 + w0 + pp] = s_t[pp*68 + c];
        }
    } else {
        __syncthreads();
        float* s_a = (float*)&s_i4[0];       // [p][c] stride 68
        s_a[p*68 + 2*tx]     = accx;
        s_a[p*68 + 2*tx + 1] = accy;
        __syncthreads();
        float2 bp = *(const float2*)(bpw + 2*tx);
        float rx = bp.x, ry = bp.y;
        const float* pwp = (const float*)g_wpwT + 2*tx;
#pragma unroll 8
        for (int c = 0; c < 64; ++c) {
            float a = s_a[p*68 + c];
            float2 pwv = *(const float2*)(pwp + c*64);
            rx += a * pwv.x;
            ry += a * pwv.y;
        }
        float* s_t = (float*)&s_wh[0][0];    // [p][o] stride 68
        s_t[p*68 + 2*tx]     = rx;
        s_t[p*68 + 2*tx + 1] = ry;
        __syncthreads();
        for (int v = tid; v < 1024; v += 512) {
            int c = v >> 4, pp = v & 15;
            int gi = ((b*64 + c)*64 + h)*64 + w0 + pp;
            outF[gi] = x[gi] * s_t[pp*68 + c];
        }
    }
}

// ---------------- launch ----------------
extern "C" void kernel_launch(void* const* d_in, const int* in_sizes, int n_in,
                              void* d_out, int out_size) {
    const float* x      = (const float*)d_in[0];
    const float* w_off0 = (const float*)d_in[1];
    const float* b_off0 = (const float*)d_in[2];
    const float* w_dw0  = (const float*)d_in[3];
    const float* b_dw0  = (const float*)d_in[4];
    const float* w_off1 = (const float*)d_in[5];
    const float* b_off1 = (const float*)d_in[6];
    const float* w_dw1  = (const float*)d_in[7];
    const float* b_dw1  = (const float*)d_in[8];
    const float* w_pw   = (const float*)d_in[9];
    const float* b_pw   = (const float*)d_in[10];
    float* out = (float*)d_out;

    prep_transpose_kernel<<<256 + 234, 256>>>(x, w_off0, w_off1, w_dw0, w_dw1, w_pw);

    dim3 cb(16, 13);
    offconv0_kernel<<<dim3(64, NB, 2), cb>>>(x, b_off0);

    deform_kernel<5, 1, false><<<dim3(4, 64, NB), dim3(32, 16)>>>(b_dw0, nullptr, nullptr, nullptr);

    offconv1_kernel<<<dim3(64, NB, 2), cb>>>(b_off1);

    deform_kernel<7, 3, true><<<dim3(4, 64, NB), dim3(32, 16)>>>(b_dw1, out, x, b_pw);
}

// round 16
// speedup vs baseline: 1.1907x; 1.0718x over previous
#include <cuda_runtime.h>
#include <cuda_fp16.h>
#include <cstdint>

#define NB 4
#define NC 64
#define NH 64
#define NW 64
#define NHW 4096

// ---- packed fp32x2 helpers (PTX-only; ptxas never auto-fuses) ----
#define PACK2(d, v)   asm("mov.b64 %0, {%1, %1};" : "=l"(d) : "r"(__float_as_uint(v)))
#define UNPACK2(l_, h_, in_) do { unsigned _ulo, _uhi; \
    asm("mov.b64 {%0, %1}, %2;" : "=r"(_ulo), "=r"(_uhi) : "l"(in_)); \
    l_ = __uint_as_float(_ulo); h_ = __uint_as_float(_uhi); } while (0)
#define FMA2(d, a, b, c) asm("fma.rn.f32x2 %0, %1, %2, %3;" : "=l"(d) : "l"(a), "l"(b), "l"(c))
#define MUL2(d, a, b)    asm("mul.rn.f32x2 %0, %1, %2;"     : "=l"(d) : "l"(a), "l"(b))

#define OFF0_QS (NB*50*NHW)
#define OFF1_QS (NB*98*NHW)

// ---------------- device scratch (no allocations allowed anywhere) ----------------
__device__ __align__(16) __half g_xT[NB*NHW*NC];     // x in NHWC, fp16 (gather source)
__device__ __align__(16) float g_attn0[NB*NC*NHW];   // attn after deform0, NCHW fp32
__device__ __align__(16) __half g_attn0T[NB*NHW*NC]; // attn after deform0, NHWC fp16
__device__ __align__(16) float g_off0p[4*OFF0_QS];   // 4 C-partials (q=0 carries bias)
__device__ __align__(16) float g_off1p[4*OFF1_QS];
__device__ __align__(16) float g_wT0[576*52];        // [c*9+tap][o] padded 50->52
__device__ __align__(16) float g_wT1[576*104];       // [c*9+tap][o] padded 98->104
__device__ __align__(16) float g_wdw0T[25*64];       // [k][c]
__device__ __align__(16) float g_wdw1T[49*64];       // [k][c]
__device__ __align__(16) float g_wpwT[64*64];        // [c][o]

// ---------------- merged weight repack + NCHW->NHWC fp16 transpose ----------------
__global__ void prep_transpose_kernel(const float* __restrict__ x,
                                      const float* __restrict__ w_off0,
                                      const float* __restrict__ w_off1,
                                      const float* __restrict__ w_dw0,
                                      const float* __restrict__ w_dw1,
                                      const float* __restrict__ w_pw) {
    __shared__ float sm[64*65];
    if (blockIdx.x < 256) {
        int bh = blockIdx.x;
        int b = bh >> 6, h = bh & 63;
        int tid = threadIdx.x;
        for (int i = tid; i < 4096; i += 256) {
            int c = i >> 6, w = i & 63;
            sm[c*65 + w] = x[((b*64 + c)*64 + h)*64 + w];
        }
        __syncthreads();
        for (int i = tid; i < 4096; i += 256) {
            int w = i >> 6, c = i & 63;
            g_xT[(b*4096 + h*64 + w)*64 + c] = __float2half_rn(sm[c*65 + w]);
        }
    } else {
        int i = (blockIdx.x - 256) * 256 + threadIdx.x;
        if (i < 576*52) {
            int r = i / 52, o = i % 52, c = r / 9, t = r % 9;
            g_wT0[i] = (o < 50) ? w_off0[(o*64 + c)*9 + t] : 0.f;
        }
        if (i < 576*104) {
            int r = i / 104, o = i % 104, c = r / 9, t = r % 9;
            g_wT1[i] = (o < 98) ? w_off1[(o*64 + c)*9 + t] : 0.f;
        }
        if (i < 25*64) { int k = i >> 6, c = i & 63; g_wdw0T[i] = w_dw0[c*25 + k]; }
        if (i < 49*64) { int k = i >> 6, c = i & 63; g_wdw1T[i] = w_dw1[c*49 + k]; }
        if (i < 4096)  { int c = i >> 6, o = i & 63; g_wpwT[i]  = w_pw[o*64 + c]; }
    }
}

// ---------------- conv0: 3x3, 64->50, smem-staged, 4-way split-C, 4 outputs/thread ----------------
__global__ void offconv0_kernel(const float* __restrict__ xin,
                                const float* __restrict__ bias) {
    constexpr int OPAD = 52, O = 50;
    __shared__ float xs[3*8*68];      // 6528 B
    __shared__ float ws[8*9*OPAD];    // 14976 B
    const int tx = threadIdx.x, ty = threadIdx.y;
    const int tid = ty*16 + tx;       // 208 threads
    const int b = blockIdx.y, h = blockIdx.x;
    const int q = blockIdx.z;         // channel quarter: c q*16..q*16+15
    float* outp = g_off0p + q*OFF0_QS;
    const int o4 = ty*4;
    const int n4 = (8*9*OPAD) >> 2;

    unsigned long long acc[4][2];
    unsigned long long z; PACK2(z, 0.f);
#pragma unroll
    for (int j = 0; j < 4; ++j) { acc[j][0] = z; acc[j][1] = z; }

    for (int cc = 0; cc < 16; cc += 8) {
        const int c0 = q*16 + cc;
        __syncthreads();
        {
            const float4* wsrc = (const float4*)(g_wT0 + c0*9*OPAD);
            float4* wdst = (float4*)ws;
            for (int i = tid; i < n4; i += 208) wdst[i] = wsrc[i];
        }
        for (int i = tid; i < 3*8*64; i += 208) {
            int r = i >> 9, rem = i & 511, c = rem >> 6, w = rem & 63;
            int hh = h + r - 1;
            float v = 0.f;
            if (hh >= 0 && hh < 64) v = xin[((b*64 + c0 + c)*64 + hh)*64 + w];
            xs[(r*8 + c)*68 + w + 1] = v;
        }
        if (tid < 24) {
            int base = tid * 68;
            xs[base] = 0.f; xs[base+65] = 0.f; xs[base+66] = 0.f; xs[base+67] = 0.f;
        }
        __syncthreads();

        for (int c = 0; c < 8; ++c) {
            const float* xrow = xs + c*68 + 4*tx;
            const float* wrow = ws + c*9*OPAD + o4;
#pragma unroll
            for (int dy = 0; dy < 3; ++dy) {
                float4 A  = *(const float4*)(xrow + dy*(8*68));
                float2 Bv = *(const float2*)(xrow + dy*(8*68) + 4);
                float v[6] = {A.x, A.y, A.z, A.w, Bv.x, Bv.y};
                unsigned long long vv[6];
#pragma unroll
                for (int j = 0; j < 6; ++j) PACK2(vv[j], v[j]);
#pragma unroll
                for (int dx = 0; dx < 3; ++dx) {
                    ulonglong2 wv = *(const ulonglong2*)(wrow + (dy*3 + dx)*OPAD);
#pragma unroll
                    for (int j = 0; j < 4; ++j) {
                        FMA2(acc[j][0], vv[j+dx], wv.x, acc[j][0]);
                        FMA2(acc[j][1], vv[j+dx], wv.y, acc[j][1]);
                    }
                }
            }
        }
    }

    float a0, a1, a2, a3;
#pragma unroll
    for (int j = 0; j < 4; ++j) {
        UNPACK2(a0, a1, acc[j][0]);
        UNPACK2(a2, a3, acc[j][1]);
        float r4[4] = {a0, a1, a2, a3};
#pragma unroll
        for (int oo = 0; oo < 4; ++oo) {
            int o = o4 + oo;
            if (o >= O) break;
            float bb = (q == 0) ? bias[o] : 0.f;
            outp[((b*O + o)*64 + h)*64 + 4*tx + j] = r4[oo] + bb;
        }
    }
}

// ---------------- conv1: 3x3, 64->98, smem-staged, 4-way split-C, 8 outputs/thread ----------------
__global__ void offconv1_kernel(const float* __restrict__ bias) {
    constexpr int OPAD = 104, O = 98;
    __shared__ float xs[3*8*68];      // 6528 B
    __shared__ float ws[8*9*OPAD];    // 29952 B
    const int tx = threadIdx.x, ty = threadIdx.y;
    const int tid = ty*16 + tx;       // 208 threads
    const int b = blockIdx.y, h = blockIdx.x;
    const int q = blockIdx.z;
    float* outp = g_off1p + q*OFF1_QS;
    const int o8 = ty*8;
    const int n4 = (8*9*OPAD) >> 2;   // 1872

    unsigned long long acc[4][4];     // [pixel j][o-pair]
    unsigned long long z; PACK2(z, 0.f);
#pragma unroll
    for (int j = 0; j < 4; ++j)
#pragma unroll
        for (int qq = 0; qq < 4; ++qq) acc[j][qq] = z;

    for (int cc = 0; cc < 16; cc += 8) {
        const int c0 = q*16 + cc;
        __syncthreads();
        {
            const float4* wsrc = (const float4*)(g_wT1 + c0*9*OPAD);
            float4* wdst = (float4*)ws;
            for (int i = tid; i < n4; i += 208) wdst[i] = wsrc[i];
        }
        for (int i = tid; i < 3*8*64; i += 208) {
            int r = i >> 9, rem = i & 511, c = rem >> 6, w = rem & 63;
            int hh = h + r - 1;
            float v = 0.f;
            if (hh >= 0 && hh < 64) v = g_attn0[((b*64 + c0 + c)*64 + hh)*64 + w];
            xs[(r*8 + c)*68 + w + 1] = v;
        }
        if (tid < 24) {
            int base = tid * 68;
            xs[base] = 0.f; xs[base+65] = 0.f; xs[base+66] = 0.f; xs[base+67] = 0.f;
        }
        __syncthreads();

        for (int c = 0; c < 8; ++c) {
            const float* xrow = xs + c*68 + 4*tx;
            const float* wrow = ws + c*9*OPAD + o8;
#pragma unroll
            for (int dy = 0; dy < 3; ++dy) {
                float4 A  = *(const float4*)(xrow + dy*(8*68));
                float2 Bv = *(const float2*)(xrow + dy*(8*68) + 4);
                float v[6] = {A.x, A.y, A.z, A.w, Bv.x, Bv.y};
                unsigned long long vv[6];
#pragma unroll
                for (int j = 0; j < 6; ++j) PACK2(vv[j], v[j]);
#pragma unroll
                for (int dx = 0; dx < 3; ++dx) {
                    ulonglong2 w01 = *(const ulonglong2*)(wrow + (dy*3 + dx)*OPAD);
                    ulonglong2 w23 = *(const ulonglong2*)(wrow + (dy*3 + dx)*OPAD + 4);
#pragma unroll
                    for (int j = 0; j < 4; ++j) {
                        FMA2(acc[j][0], vv[j+dx], w01.x, acc[j][0]);
                        FMA2(acc[j][1], vv[j+dx], w01.y, acc[j][1]);
                        FMA2(acc[j][2], vv[j+dx], w23.x, acc[j][2]);
                        FMA2(acc[j][3], vv[j+dx], w23.y, acc[j][3]);
                    }
                }
            }
        }
    }

#pragma unroll
    for (int j = 0; j < 4; ++j) {
        float r8[8];
        UNPACK2(r8[0], r8[1], acc[j][0]);
        UNPACK2(r8[2], r8[3], acc[j][1]);
        UNPACK2(r8[4], r8[5], acc[j][2]);
        UNPACK2(r8[6], r8[7], acc[j][3]);
#pragma unroll
        for (int oo = 0; oo < 8; ++oo) {
            int o = o8 + oo;
            if (o < O) {
                float bb = (q == 0) ? bias[o] : 0.f;
                outp[((b*O + o)*64 + h)*64 + 4*tx + j] = r8[oo] + bb;
            }
        }
    }
}

// ---------------- deformable depthwise conv: tap precompute + fp16 gathers + HFMA2 ----------------
// Proven shape: block (32,16) = 512 threads, 2 channels/thread. Offsets = sum of 4 partials.
template<int K, int DIL, bool FUSE>
__global__ void __launch_bounds__(512) deform_kernel(const float* __restrict__ bdw,
                                                     float* __restrict__ outF,
                                                     const float* __restrict__ x,
                                                     const float* __restrict__ bpw) {
    constexpr int K2  = K * K;
    constexpr int PAD = (K / 2) * DIL;
    constexpr int E   = K2 * 16;
    constexpr int QS  = FUSE ? OFF1_QS : OFF0_QS;
    __shared__ __align__(16) int4  s_i4[E];
    __shared__ __align__(16) half2 s_wh[E][4];   // lane-duplicated bilinear weights
    __shared__ float s_wdw[K2*64];

    const int tx = threadIdx.x;          // channel pair: channels 2tx, 2tx+1
    const int p  = threadIdx.y;          // pixel within block
    const int tid = p*32 + tx;
    const int b = blockIdx.z, h = blockIdx.y, w0 = blockIdx.x * 16;

    const float* wdwT = FUSE ? (const float*)g_wdw1T : (const float*)g_wdw0T;
    for (int i = tid; i < K2*64; i += 512) s_wdw[i] = wdwT[i];

    const float* offA = (FUSE ? (const float*)g_off1p : (const float*)g_off0p)
                        + (size_t)(b*2*K2)*4096 + h*64 + w0;
    for (int e = tid; e < E; e += 512) {
        int k = e >> 4, pp = e & 15;
        float oy = 0.f, ox = 0.f;
#pragma unroll
        for (int qq = 0; qq < 4; ++qq) {
            oy += offA[qq*QS + (2*k)*4096   + pp];
            ox += offA[qq*QS + (2*k+1)*4096 + pp];
        }
        float py = (float)(h - PAD + DIL*(k/K)) + oy;
        float px = (float)(w0 + pp - PAD + DIL*(k%K)) + ox;
        float fy = floorf(py), fx = floorf(px);
        float wy1 = py - fy, wx1 = px - fx;
        int y0 = (int)fy, x0i = (int)fx;
        bool yv0 = (unsigned)y0        < 64u;
        bool yv1 = (unsigned)(y0 + 1)  < 64u;
        bool xv0 = (unsigned)x0i       < 64u;
        bool xv1 = (unsigned)(x0i + 1) < 64u;
        int yc0 = min(max(y0, 0), 63),  yc1 = min(max(y0 + 1, 0), 63);
        int xc0 = min(max(x0i, 0), 63), xc1 = min(max(x0i + 1, 0), 63);
        float wy0f = 1.f - wy1, wx0f = 1.f - wx1;
        s_i4[e] = make_int4(yc0*4096 + xc0*64, yc0*4096 + xc1*64,
                            yc1*4096 + xc0*64, yc1*4096 + xc1*64);
        float m00 = (yv0 && xv0) ? wy0f*wx0f : 0.f;
        float m01 = (yv0 && xv1) ? wy0f*wx1  : 0.f;
        float m10 = (yv1 && xv0) ? wy1 *wx0f : 0.f;
        float m11 = (yv1 && xv1) ? wy1 *wx1  : 0.f;
        s_wh[e][0] = __floats2half2_rn(m00, m00);
        s_wh[e][1] = __floats2half2_rn(m01, m01);
        s_wh[e][2] = __floats2half2_rn(m10, m10);
        s_wh[e][3] = __floats2half2_rn(m11, m11);
    }
    __syncthreads();

    const __half* base = (FUSE ? (const __half*)g_attn0T : (const __half*)g_xT)
                         + (size_t)b*262144 + 2*tx;
    float accx = 0.f, accy = 0.f;
#pragma unroll 7
    for (int k = 0; k < K2; ++k) {
        int e = (k << 4) | p;
        int4  I = s_i4[e];
        half2 W0 = s_wh[e][0], W1 = s_wh[e][1], W2 = s_wh[e][2], W3 = s_wh[e][3];
        half2 g00 = *(const half2*)(base + I.x);
        half2 g01 = *(const half2*)(base + I.y);
        half2 g10 = *(const half2*)(base + I.z);
        half2 g11 = *(const half2*)(base + I.w);
        half2 v = __hmul2(g00, W0);
        v = __hfma2(g01, W1, v);
        v = __hfma2(g10, W2, v);
        v = __hfma2(g11, W3, v);
        float2 vf = __half22float2(v);
        float2 wd = *(const float2*)(s_wdw + k*64 + 2*tx);
        accx += vf.x * wd.x;
        accy += vf.y * wd.y;
    }
    float2 bd = *(const float2*)(bdw + 2*tx);
    accx += bd.x; accy += bd.y;

    if (!FUSE) {
        *(half2*)(g_attn0T + (size_t)(b*4096 + h*64 + w0 + p)*64 + 2*tx) =
            __floats2half2_rn(accx, accy);
        __syncthreads();
        float* s_t = (float*)&s_wh[0][0];    // [p][c] stride 68
        s_t[p*68 + 2*tx]     = accx;
        s_t[p*68 + 2*tx + 1] = accy;
        __syncthreads();
        for (int v = tid; v < 1024; v += 512) {
            int c = v >> 4, pp = v & 15;
            g_attn0[((b*64 + c)*64 + h)*64 + w0 + pp] = s_t[pp*68 + c];
        }
    } else {
        __syncthreads();
        float* s_a = (float*)&s_i4[0];       // [p][c] stride 68
        s_a[p*68 + 2*tx]     = accx;
        s_a[p*68 + 2*tx + 1] = accy;
        __syncthreads();
        float2 bp = *(const float2*)(bpw + 2*tx);
        float rx = bp.x, ry = bp.y;
        const float* pwp = (const float*)g_wpwT + 2*tx;
#pragma unroll 8
        for (int c = 0; c < 64; ++c) {
            float a = s_a[p*68 + c];
            float2 pwv = *(const float2*)(pwp + c*64);
            rx += a * pwv.x;
            ry += a * pwv.y;
        }
        float* s_t = (float*)&s_wh[0][0];    // [p][o] stride 68
        s_t[p*68 + 2*tx]     = rx;
        s_t[p*68 + 2*tx + 1] = ry;
        __syncthreads();
        for (int v = tid; v < 1024; v += 512) {
            int c = v >> 4, pp = v & 15;
            int gi = ((b*64 + c)*64 + h)*64 + w0 + pp;
            outF[gi] = x[gi] * s_t[pp*68 + c];
        }
    }
}

// ---------------- launch ----------------
extern "C" void kernel_launch(void* const* d_in, const int* in_sizes, int n_in,
                              void* d_out, int out_size) {
    const float* x      = (const float*)d_in[0];
    const float* w_off0 = (const float*)d_in[1];
    const float* b_off0 = (const float*)d_in[2];
    const float* w_dw0  = (const float*)d_in[3];
    const float* b_dw0  = (const float*)d_in[4];
    const float* w_off1 = (const float*)d_in[5];
    const float* b_off1 = (const float*)d_in[6];
    const float* w_dw1  = (const float*)d_in[7];
    const float* b_dw1  = (const float*)d_in[8];
    const float* w_pw   = (const float*)d_in[9];
    const float* b_pw   = (const float*)d_in[10];
    float* out = (float*)d_out;

    prep_transpose_kernel<<<256 + 234, 256>>>(x, w_off0, w_off1, w_dw0, w_dw1, w_pw);

    dim3 cb(16, 13);
    offconv0_kernel<<<dim3(64, NB, 4), cb>>>(x, b_off0);

    deform_kernel<5, 1, false><<<dim3(4, 64, NB), dim3(32, 16)>>>(b_dw0, nullptr, nullptr, nullptr);

    offconv1_kernel<<<dim3(64, NB, 4), cb>>>(b_off1);

    deform_kernel<7, 3, true><<<dim3(4, 64, NB), dim3(32, 16)>>>(b_dw1, out, x, b_pw);
}